// round 7
// baseline (speedup 1.0000x reference)
#include <cuda_runtime.h>
#include <cstdint>

// Problem constants (fixed by the dataset)
#define LL 256

#define THREADS 128   // 4 warps = 2 warp-pairs = 2 batch elements per block
typedef unsigned long long ull;

// ---------- f32x2 packed helpers (Blackwell packed fp32 pipe) ----------
__device__ __forceinline__ ull pack2(float a, float b) {
    ull r;
    asm("mov.b64 %0, {%1, %2};" : "=l"(r)
        : "r"(__float_as_uint(a)), "r"(__float_as_uint(b)));
    return r;
}
__device__ __forceinline__ void unpack2(ull v, float& a, float& b) {
    unsigned int x, y;
    asm("mov.b64 {%0, %1}, %2;" : "=r"(x), "=r"(y) : "l"(v));
    a = __uint_as_float(x);
    b = __uint_as_float(y);
}
__device__ __forceinline__ ull fma2(ull a, ull b, ull c) {
    ull d;
    asm("fma.rn.f32x2 %0, %1, %2, %3;" : "=l"(d) : "l"(a), "l"(b), "l"(c));
    return d;
}
__device__ __forceinline__ ull add2(ull a, ull b) {
    ull d;
    asm("add.rn.f32x2 %0, %1, %2;" : "=l"(d) : "l"(a), "l"(b));
    return d;
}

// HW tanh (MUFU.TANH): ~1e-4 abs error, 1 MUFU op
__device__ __forceinline__ float tanh_fast(float x) {
    float y;
    asm("tanh.approx.f32 %0, %1;" : "=f"(y) : "f"(x));
    return y;
}

// Deferred output head: butterfly-reduce staged (h*wo0, h*wo1), elu +
// 2-class gathered log-softmax. wmask=0 drops the priming pend.
__device__ __forceinline__ float head_update(ull pp, int cur,
                                             float bo0, float bo1,
                                             float wmask, float logp) {
#pragma unroll
    for (int d = 16; d > 0; d >>= 1) {
        ull q = __shfl_xor_sync(0xffffffffu, pp, d);
        pp = add2(pp, q);
    }
    float p0, p1;
    unpack2(pp, p0, p1);
    p0 += bo0;
    p1 += bo1;
    float e0 = (p0 > 0.f) ? p0 : (__expf(p0) - 1.f);
    float e1 = (p1 > 0.f) ? p1 : (__expf(p1) - 1.f);
    float d = cur ? (e0 - e1) : (e1 - e0);   // e_other - e_sel
    return fmaf(wmask, -__logf(1.f + __expf(d)), logp);
}

// Layout: a PAIR of warps owns one batch element. Lane j = hidden unit j in
// both warps. Warp role r holds register weights for Wh rows k = r*16..r*16+15
// (64 regs instead of 128 -> 5 blocks/SM, 20 warps/SM). Per step each warp:
//   partial gates over its k-half (8 broadcast LDS.128 + 32 FFMA2)
//   -> STS.128 partial -> __syncthreads -> LDS.128 partner partial -> combine
//   -> full activation tail (redundant in both warps, keeps h local)
//   -> publish its own h-half for next step (no second exchange needed).
// The deferred log-softmax head alternates between the two warps by step
// parity and runs in the barrier-wait shadow.
__global__ void __launch_bounds__(THREADS, 5)
lstm_kernel(const int* __restrict__ x,       // [B, L] spins in {0,1}
            const float* __restrict__ Wi,    // [2, 128]
            const float* __restrict__ Wh,    // [32, 128]
            const float* __restrict__ bh,    // [128]
            const float* __restrict__ Wo,    // [32, 2]
            const float* __restrict__ bo,    // [2]
            float* __restrict__ out)         // [B]
{
    __shared__ ulonglong2 s_init[3 * 32];        // prescaled (Wi[sel]+bh) rows
    __shared__ ulonglong2 s_part[2][2][2][32];   // [pair][buf][role][lane]
    __shared__ ulonglong2 s_h[4][2][8];          // [warp][buf][kk/2] (h,h) pairs
    __shared__ unsigned char s_x[2 * LL];
    __shared__ float s_logp[2];

    const int tid = threadIdx.x;
    const int lane = tid & 31;
    const int warp = tid >> 5;
    const int pair = warp >> 1;
    const int role = warp & 1;
    const int j = lane;

    // ---- setup: init-row table (prescaled: 0.5 on i,f,o; 1.0 on g) ----
    if (tid < 96) {
        int s = tid >> 5;        // 0,1 = spin rows, 2 = bh-only (t=0)
        int jj = tid & 31;
        float ai = bh[jj], af = bh[32 + jj], ag = bh[64 + jj], ao = bh[96 + jj];
        if (s < 2) {
            ai += Wi[s * 128 + jj];
            af += Wi[s * 128 + 32 + jj];
            ag += Wi[s * 128 + 64 + jj];
            ao += Wi[s * 128 + 96 + jj];
        }
        ulonglong2 v;
        v.x = pack2(0.5f * ai, 0.5f * af);
        v.y = pack2(ag, 0.5f * ao);
        s_init[s * 32 + jj] = v;
    }
    {
        const int base = blockIdx.x * 2 * LL;
        for (int idx = tid; idx < 2 * LL; idx += THREADS)
            s_x[idx] = (unsigned char)x[base + idx];
    }

    // ---- register-resident recurrent weights for MY k-half (prescaled) ----
    const int kbase = role * 16;
    ull wif[16], wgo[16];
#pragma unroll
    for (int kk = 0; kk < 16; kk++) {
        const float* r = Wh + (kbase + kk) * 128;
        wif[kk] = pack2(0.5f * r[j], 0.5f * r[32 + j]);
        wgo[kk] = pack2(r[64 + j], 0.5f * r[96 + j]);
    }
    const ull wo01 = pack2(Wo[2 * j], Wo[2 * j + 1]);
    const float bo0 = bo[0];
    const float bo1 = bo[1];

    __syncthreads();

    // gate-init rows: only role 0 carries the (Wi[sel]+bh) term; role 1 -> 0
    ull selif, selgo;
    if (role == 0) {
        ulonglong2 v = s_init[2 * 32 + lane];   // t=0: bh-only row
        selif = v.x;
        selgo = v.y;
    } else {
        selif = 0ull;
        selgo = 0ull;
    }

    float h = 0.f, c = 0.f, logp = 0.f, wmask = 0.f;
    ull pend = 0ull;
    int cur_pend = 0;

    // initial h = 0 table for step 0
    if ((lane >> 4) == role)
        reinterpret_cast<ull*>(s_h[warp][0])[lane & 15] = 0ull;
    __syncwarp();

    const unsigned char* xb = s_x + pair * LL;

#pragma unroll 1
    for (int t = 0; t < LL; t += 2) {
#pragma unroll
        for (int half = 0; half < 2; half++) {
            const ulonglong2* hb = s_h[warp][half];

            // ---- partial gates over my k-half ----
            ull a0 = selif, a1 = 0ull, g0 = selgo, g1 = 0ull;
#pragma unroll
            for (int kk = 0; kk < 16; kk += 2) {
                ulonglong2 hh = hb[kk >> 1];   // broadcast LDS.128
                a0 = fma2(hh.x, wif[kk], a0);
                g0 = fma2(hh.x, wgo[kk], g0);
                a1 = fma2(hh.y, wif[kk + 1], a1);
                g1 = fma2(hh.y, wgo[kk + 1], g1);
            }
            ull pa = add2(a0, a1);
            ull pg = add2(g0, g1);
            ulonglong2 mp;
            mp.x = pa;
            mp.y = pg;
            s_part[pair][half][role][lane] = mp;   // STS.128

            // deferred head of the previous step (alternating role);
            // runs in the barrier-wait shadow
            if (role == (half ^ 1))
                logp = head_update(pend, cur_pend, bo0, bo1, wmask, logp);

            __syncthreads();

            // ---- combine with partner's partial ----
            ulonglong2 op = s_part[pair][half][role ^ 1][lane];  // LDS.128
            ull aif = add2(pa, op.x);
            ull ago = add2(pg, op.y);

            float gi, gf, gg, go;
            unpack2(aif, gi, gf);
            unpack2(ago, gg, go);
            float si = fmaf(0.5f, tanh_fast(gi), 0.5f);   // prescaled sigmoid
            float sf = fmaf(0.5f, tanh_fast(gf), 0.5f);
            float so = fmaf(0.5f, tanh_fast(go), 0.5f);
            float tg = tanh_fast(gg);
            c = fmaf(sf, c, si * tg);
            h = so * tanh_fast(c);

            // publish my h-half for next step (self-consumed, warp-local)
            ull hpair = pack2(h, h);
            if ((lane >> 4) == role)
                reinterpret_cast<ull*>(s_h[warp][half ^ 1])[lane & 15] = hpair;
            __syncwarp();

            // stage this step's output head
            pend = fma2(hpair, wo01, 0ull);
            int cur = (int)xb[t + half];
            cur_pend = cur;
            wmask = 1.f;
            if (role == 0) {
                ulonglong2 vn = s_init[cur * 32 + lane];
                selif = vn.x;
                selgo = vn.y;
            }
        }
    }

    // flush: pend of step 255 (odd parity) belongs to role 1
    if (role == 1) {
        logp = head_update(pend, cur_pend, bo0, bo1, wmask, logp);
        if (lane == 0)
            s_logp[pair] = logp;
    }
    __syncthreads();
    if (role == 0 && lane == 0) {
        out[blockIdx.x * 2 + pair] = 0.5f * (logp + s_logp[pair]);
    }
}

extern "C" void kernel_launch(void* const* d_in, const int* in_sizes, int n_in,
                              void* d_out, int out_size) {
    const int* x = (const int*)d_in[0];
    const float* Wi = (const float*)d_in[1];
    const float* Wh = (const float*)d_in[2];
    const float* bh = (const float*)d_in[3];
    const float* Wo = (const float*)d_in[4];
    const float* bo = (const float*)d_in[5];
    float* out = (float*)d_out;

    const int batch = in_sizes[0] / LL;   // 4096
    const int blocks = batch / 2;         // 2048 (2 batch elements per block)

    lstm_kernel<<<blocks, THREADS>>>(x, Wi, Wh, bh, Wo, bo, out);
}

// round 8
// speedup vs baseline: 1.4065x; 1.4065x over previous
#include <cuda_runtime.h>
#include <cstdint>

// Problem constants (fixed by the dataset)
#define LL 256

#define WARPS_PER_BLOCK 4
#define THREADS_PER_BLOCK (WARPS_PER_BLOCK * 32)
#define BATCH_PER_WARP 2
#define BATCH_PER_BLOCK (WARPS_PER_BLOCK * BATCH_PER_WARP)  // 8
typedef unsigned long long ull;

// ---------- f32x2 packed helpers (Blackwell packed fp32 pipe) ----------
__device__ __forceinline__ ull pack2(float a, float b) {
    ull r;
    asm("mov.b64 %0, {%1, %2};" : "=l"(r)
        : "r"(__float_as_uint(a)), "r"(__float_as_uint(b)));
    return r;
}
__device__ __forceinline__ void unpack2(ull v, float& a, float& b) {
    unsigned int x, y;
    asm("mov.b64 {%0, %1}, %2;" : "=r"(x), "=r"(y) : "l"(v));
    a = __uint_as_float(x);
    b = __uint_as_float(y);
}
__device__ __forceinline__ ull fma2(ull a, ull b, ull c) {
    ull d;
    asm("fma.rn.f32x2 %0, %1, %2, %3;" : "=l"(d) : "l"(a), "l"(b), "l"(c));
    return d;
}
__device__ __forceinline__ ull add2(ull a, ull b) {
    ull d;
    asm("add.rn.f32x2 %0, %1, %2;" : "=l"(d) : "l"(a), "l"(b));
    return d;
}

// HW tanh (MUFU.TANH): ~1e-4 abs error, 1 MUFU op
__device__ __forceinline__ float tanh_fast(float x) {
    float y;
    asm("tanh.approx.f32 %0, %1;" : "=f"(y) : "f"(x));
    return y;
}

// Deferred output head: butterfly-reduce staged (h*wo0, h*wo1), elu +
// 2-class gathered log-softmax. wmask=0 drops the priming pend.
__device__ __forceinline__ float head_update(ull pp, int cur,
                                             float bo0, float bo1,
                                             float wmask, float logp) {
#pragma unroll
    for (int d = 16; d > 0; d >>= 1) {
        ull q = __shfl_xor_sync(0xffffffffu, pp, d);
        pp = add2(pp, q);
    }
    float p0, p1;
    unpack2(pp, p0, p1);
    p0 += bo0;
    p1 += bo1;
    float e0 = (p0 > 0.f) ? p0 : (__expf(p0) - 1.f);
    float e1 = (p1 > 0.f) ? p1 : (__expf(p1) - 1.f);
    float d = cur ? (e0 - e1) : (e1 - e0);   // e_other - e_sel
    return fmaf(wmask, -__logf(1.f + __expf(d)), logp);
}

// Layout: warp = TWO batch elements (pure ILP; warp fully self-contained,
// no cross-warp sync — that's what regressed R7). Lane j = hidden unit j.
// Register weights as in R6 (128 regs, prescaled 0.5 on i,f,o columns).
// h-table entry per k: ulonglong2 {(h_k^b0,h_k^b0),(h_k^b1,h_k^b1)} -> ONE
// broadcast LDS.128 per k feeds both batches' f32x2 fma chains (8 chains).
// Output heads (both batches) stay software-pipelined one step behind.
__global__ void __launch_bounds__(THREADS_PER_BLOCK, 2)
lstm_kernel(const int* __restrict__ x,       // [B, L] spins in {0,1}
            const float* __restrict__ Wi,    // [2, 128]
            const float* __restrict__ Wh,    // [32, 128]
            const float* __restrict__ bh,    // [128]
            const float* __restrict__ Wo,    // [32, 2]
            const float* __restrict__ bo,    // [2]
            float* __restrict__ out)         // [B]
{
    __shared__ ulonglong2 s_init[3 * 32];           // prescaled (Wi[sel]+bh)
    __shared__ ulonglong2 s_h[WARPS_PER_BLOCK][2][32];  // [warp][buf][k]
    __shared__ unsigned char s_x[BATCH_PER_BLOCK * LL];

    const int tid = threadIdx.x;
    const int lane = tid & 31;
    const int warp = tid >> 5;
    const int j = lane;

    // ---- setup: init-row table (prescaled: 0.5 on i,f,o; 1.0 on g) ----
    if (tid < 96) {
        int s = tid >> 5;        // 0,1 = spin rows, 2 = bh-only (t=0)
        int jj = tid & 31;
        float ai = bh[jj], af = bh[32 + jj], ag = bh[64 + jj], ao = bh[96 + jj];
        if (s < 2) {
            ai += Wi[s * 128 + jj];
            af += Wi[s * 128 + 32 + jj];
            ag += Wi[s * 128 + 64 + jj];
            ao += Wi[s * 128 + 96 + jj];
        }
        ulonglong2 v;
        v.x = pack2(0.5f * ai, 0.5f * af);
        v.y = pack2(ag, 0.5f * ao);
        s_init[s * 32 + jj] = v;
    }
    {
        const int base = blockIdx.x * BATCH_PER_BLOCK * LL;
        for (int idx = tid; idx < BATCH_PER_BLOCK * LL; idx += THREADS_PER_BLOCK)
            s_x[idx] = (unsigned char)x[base + idx];
    }
    __syncthreads();

    // ---- register-resident recurrent weights (prescaled), as in R6 ----
    ull wif[32], wgo[32];
#pragma unroll
    for (int k = 0; k < 32; k++) {
        const float* r = Wh + k * 128;
        wif[k] = pack2(0.5f * r[j], 0.5f * r[32 + j]);
        wgo[k] = pack2(r[64 + j], 0.5f * r[96 + j]);
    }
    const ull wo01 = pack2(Wo[2 * j], Wo[2 * j + 1]);
    const float bo0 = bo[0];
    const float bo1 = bo[1];

    const unsigned char* xb0 = s_x + (warp * 2 + 0) * LL;
    const unsigned char* xb1 = s_x + (warp * 2 + 1) * LL;

    float h0 = 0.f, c0 = 0.f, logp0 = 0.f;
    float h1 = 0.f, c1 = 0.f, logp1 = 0.f;
    float wmask = 0.f;
    ull pend0 = 0ull, pend1 = 0ull;
    int curp0 = 0, curp1 = 0;

    // t=0 gate init for both batches: bh-only row (row 2)
    ulonglong2 v0 = s_init[2 * 32 + lane];
    ull selif0 = v0.x, selgo0 = v0.y;
    ull selif1 = v0.x, selgo1 = v0.y;

#pragma unroll 1
    for (int t = 0; t < LL; t += 2) {
#pragma unroll
        for (int half = 0; half < 2; half++) {
            // publish both batches' (h,h) pairs: one STS.128 per lane
            ulonglong2 hp;
            hp.x = pack2(h0, h0);
            hp.y = pack2(h1, h1);
            s_h[warp][half][lane] = hp;
            __syncwarp();
            const ulonglong2* hb = s_h[warp][half];

            // deferred output heads of the PREVIOUS step (both batches);
            // SHFL/MUFU latency overlaps the fma loop below
            logp0 = head_update(pend0, curp0, bo0, bo1, wmask, logp0);
            logp1 = head_update(pend1, curp1, bo0, bo1, wmask, logp1);

            // ---- gate fma loop: 8 independent chains (2 batches x 4) ----
            ull aif0 = selif0, ago0 = selgo0;
            ull aif1 = selif1, ago1 = selgo1;
#pragma unroll
            for (int k = 0; k < 32; k++) {
                ulonglong2 hh = hb[k];   // broadcast LDS.128: both batches' h_k
                aif0 = fma2(hh.x, wif[k], aif0);
                ago0 = fma2(hh.x, wgo[k], ago0);
                aif1 = fma2(hh.y, wif[k], aif1);
                ago1 = fma2(hh.y, wgo[k], ago1);
            }

            // ---- batch 0 tail ----
            {
                float gi, gf, gg, go;
                unpack2(aif0, gi, gf);
                unpack2(ago0, gg, go);
                float si = fmaf(0.5f, tanh_fast(gi), 0.5f);
                float sf = fmaf(0.5f, tanh_fast(gf), 0.5f);
                float so = fmaf(0.5f, tanh_fast(go), 0.5f);
                float tg = tanh_fast(gg);
                c0 = fmaf(sf, c0, si * tg);
                h0 = so * tanh_fast(c0);
                pend0 = fma2(pack2(h0, h0), wo01, 0ull);
                int cur = (int)xb0[t + half];
                curp0 = cur;
                ulonglong2 vn = s_init[cur * 32 + lane];
                selif0 = vn.x;
                selgo0 = vn.y;
            }
            // ---- batch 1 tail (independent of batch 0's) ----
            {
                float gi, gf, gg, go;
                unpack2(aif1, gi, gf);
                unpack2(ago1, gg, go);
                float si = fmaf(0.5f, tanh_fast(gi), 0.5f);
                float sf = fmaf(0.5f, tanh_fast(gf), 0.5f);
                float so = fmaf(0.5f, tanh_fast(go), 0.5f);
                float tg = tanh_fast(gg);
                c1 = fmaf(sf, c1, si * tg);
                h1 = so * tanh_fast(c1);
                pend1 = fma2(pack2(h1, h1), wo01, 0ull);
                int cur = (int)xb1[t + half];
                curp1 = cur;
                ulonglong2 vn = s_init[cur * 32 + lane];
                selif1 = vn.x;
                selgo1 = vn.y;
            }
            wmask = 1.f;
        }
    }

    // flush the last step's pends
    logp0 = head_update(pend0, curp0, bo0, bo1, wmask, logp0);
    logp1 = head_update(pend1, curp1, bo0, bo1, wmask, logp1);

    if (lane == 0) {
        const int b0 = blockIdx.x * BATCH_PER_BLOCK + warp * 2;
        out[b0] = 0.5f * logp0;
        out[b0 + 1] = 0.5f * logp1;
    }
}

extern "C" void kernel_launch(void* const* d_in, const int* in_sizes, int n_in,
                              void* d_out, int out_size) {
    const int* x = (const int*)d_in[0];
    const float* Wi = (const float*)d_in[1];
    const float* Wh = (const float*)d_in[2];
    const float* bh = (const float*)d_in[3];
    const float* Wo = (const float*)d_in[4];
    const float* bo = (const float*)d_in[5];
    float* out = (float*)d_out;

    const int batch = in_sizes[0] / LL;              // 4096
    const int blocks = batch / BATCH_PER_BLOCK;      // 512

    lstm_kernel<<<blocks, THREADS_PER_BLOCK>>>(x, Wi, Wh, bh, Wo, bo, out);
}

// round 9
// speedup vs baseline: 1.4413x; 1.0247x over previous
#include <cuda_runtime.h>
#include <cstdint>

// Problem constants (fixed by the dataset)
#define LL 256

#define WARPS_PER_BLOCK 4
#define THREADS_PER_BLOCK (WARPS_PER_BLOCK * 32)   // 1 warp = 1 batch element
typedef unsigned long long ull;

// ---------- f32x2 packed helpers (Blackwell packed fp32 pipe) ----------
__device__ __forceinline__ ull pack2(float a, float b) {
    ull r;
    asm("mov.b64 %0, {%1, %2};" : "=l"(r)
        : "r"(__float_as_uint(a)), "r"(__float_as_uint(b)));
    return r;
}
__device__ __forceinline__ void unpack2(ull v, float& a, float& b) {
    unsigned int x, y;
    asm("mov.b64 {%0, %1}, %2;" : "=r"(x), "=r"(y) : "l"(v));
    a = __uint_as_float(x);
    b = __uint_as_float(y);
}
__device__ __forceinline__ ull fma2(ull a, ull b, ull c) {
    ull d;
    asm("fma.rn.f32x2 %0, %1, %2, %3;" : "=l"(d) : "l"(a), "l"(b), "l"(c));
    return d;
}
__device__ __forceinline__ ull add2(ull a, ull b) {
    ull d;
    asm("add.rn.f32x2 %0, %1, %2;" : "=l"(d) : "l"(a), "l"(b));
    return d;
}

// HW tanh (MUFU.TANH): ~1e-4 abs error, 1 MUFU op
__device__ __forceinline__ float tanh_fast(float x) {
    float y;
    asm("tanh.approx.f32 %0, %1;" : "=f"(y) : "f"(x));
    return y;
}

// Deferred output head: butterfly-reduce staged (h*wo0, h*wo1), elu +
// 2-class gathered log-softmax. wmask=0 drops the priming pend.
__device__ __forceinline__ float head_update(ull pp, int cur,
                                             float bo0, float bo1,
                                             float wmask, float logp) {
#pragma unroll
    for (int d = 16; d > 0; d >>= 1) {
        ull q = __shfl_xor_sync(0xffffffffu, pp, d);
        pp = add2(pp, q);
    }
    float p0, p1;
    unpack2(pp, p0, p1);
    p0 += bo0;
    p1 += bo1;
    float e0 = (p0 > 0.f) ? p0 : (__expf(p0) - 1.f);
    float e1 = (p1 > 0.f) ? p1 : (__expf(p1) - 1.f);
    float d = cur ? (e0 - e1) : (e1 - e0);   // e_other - e_sel
    return fmaf(wmask, -__logf(1.f + __expf(d)), logp);
}

// Layout: warp = one batch element (R6 optimum). Lane j owns hidden unit j.
// NEW even/odd scheme: h published as SCALARS (STS.32); the table is read as
// (h_2m, h_2m+1) f32x2 pairs via 8 broadcast LDS.128 per step (was 16, no
// duplication, no packs). Weights paired along k per gate:
//   w_g[m] = (Wh[2m][col_g(j)], Wh[2m+1][col_g(j)])  (0.5-prescaled on i,f,o)
// fma2(h_pair, w_pair, acc) accumulates even-k in lo, odd-k in hi; one
// horizontal add per gate folds them with the init row (per-gate scalars).
// 8 independent chains of depth 8. Output head stays pipelined 1 step behind.
__global__ void __launch_bounds__(THREADS_PER_BLOCK, 3)
lstm_kernel(const int* __restrict__ x,       // [B, L] spins in {0,1}
            const float* __restrict__ Wi,    // [2, 128]
            const float* __restrict__ Wh,    // [32, 128]
            const float* __restrict__ bh,    // [128]
            const float* __restrict__ Wo,    // [32, 2]
            const float* __restrict__ bo,    // [2]
            float* __restrict__ out)         // [B]
{
    __shared__ float4 s_init[3 * 32];               // [sel][lane]: (i,f,g,o) prescaled
    __shared__ float s_hf[WARPS_PER_BLOCK][2][32];  // scalar h, double-buffered
    __shared__ unsigned char s_x[WARPS_PER_BLOCK * LL];

    const int tid = threadIdx.x;
    const int lane = tid & 31;
    const int warp = tid >> 5;
    const int b_glob = blockIdx.x * WARPS_PER_BLOCK + warp;
    const int j = lane;

    // ---- setup: init-row table, per-gate scalars (0.5 on i,f,o; 1.0 on g) ----
    if (tid < 96) {
        int s = tid >> 5;        // 0,1 = spin rows, 2 = bh-only (t=0)
        int jj = tid & 31;
        float ai = bh[jj], af = bh[32 + jj], ag = bh[64 + jj], ao = bh[96 + jj];
        if (s < 2) {
            ai += Wi[s * 128 + jj];
            af += Wi[s * 128 + 32 + jj];
            ag += Wi[s * 128 + 64 + jj];
            ao += Wi[s * 128 + 96 + jj];
        }
        s_init[s * 32 + jj] = make_float4(0.5f * ai, 0.5f * af, ag, 0.5f * ao);
    }
    {
        const int base = blockIdx.x * WARPS_PER_BLOCK * LL;
        for (int idx = tid; idx < WARPS_PER_BLOCK * LL; idx += THREADS_PER_BLOCK)
            s_x[idx] = (unsigned char)x[base + idx];
    }
    __syncthreads();

    const unsigned char* xb = s_x + warp * LL;

    // ---- register-resident weights: k-paired per gate (prescaled) ----
    ull wpi[16], wpf[16], wpg[16], wpo[16];
#pragma unroll
    for (int m = 0; m < 16; m++) {
        const float* r0 = Wh + (2 * m) * 128;
        const float* r1 = Wh + (2 * m + 1) * 128;
        wpi[m] = pack2(0.5f * r0[j], 0.5f * r1[j]);
        wpf[m] = pack2(0.5f * r0[32 + j], 0.5f * r1[32 + j]);
        wpg[m] = pack2(r0[64 + j], r1[64 + j]);
        wpo[m] = pack2(0.5f * r0[96 + j], 0.5f * r1[96 + j]);
    }
    const ull wo01 = pack2(Wo[2 * j], Wo[2 * j + 1]);
    const float bo0 = bo[0];
    const float bo1 = bo[1];

    float h = 0.f, c = 0.f, logp = 0.f, wmask = 0.f;
    ull pend = 0ull;
    int cur_pend = 0;

    // t=0 gate init: bh-only row (row 2)
    float4 iv = s_init[2 * 32 + lane];

    const ulonglong2* hb0 = reinterpret_cast<const ulonglong2*>(s_hf[warp][0]);
    const ulonglong2* hb1 = reinterpret_cast<const ulonglong2*>(s_hf[warp][1]);

#pragma unroll 1
    for (int t = 0; t < LL; t += 2) {
#pragma unroll
        for (int half = 0; half < 2; half++) {
            // publish my scalar h (STS.32, 1 wavefront)
            s_hf[warp][half][lane] = h;
            __syncwarp();
            const ulonglong2* hb = half ? hb1 : hb0;

            // deferred output head of the PREVIOUS step (independent; its
            // SHFL/MUFU latency overlaps the fma loop below)
            logp = head_update(pend, cur_pend, bo0, bo1, wmask, logp);

            // ---- gate fma loop: 8 chains of depth 8, 8 broadcast LDS.128 ----
            ull ai0 = 0ull, af0 = 0ull, ag0 = 0ull, ao0 = 0ull;
            ull ai1 = 0ull, af1 = 0ull, ag1 = 0ull, ao1 = 0ull;
#pragma unroll
            for (int m = 0; m < 8; m++) {
                ulonglong2 hh = hb[m];   // (h4m,h4m+1),(h4m+2,h4m+3)
                ai0 = fma2(hh.x, wpi[2 * m], ai0);
                af0 = fma2(hh.x, wpf[2 * m], af0);
                ag0 = fma2(hh.x, wpg[2 * m], ag0);
                ao0 = fma2(hh.x, wpo[2 * m], ao0);
                ai1 = fma2(hh.y, wpi[2 * m + 1], ai1);
                af1 = fma2(hh.y, wpf[2 * m + 1], af1);
                ag1 = fma2(hh.y, wpg[2 * m + 1], ag1);
                ao1 = fma2(hh.y, wpo[2 * m + 1], ao1);
            }

            // ---- horizontal combine + init, then activation tail ----
            float lo, hi;
            ull ti = add2(ai0, ai1);
            unpack2(ti, lo, hi);
            float gi = iv.x + lo + hi;
            ull tf = add2(af0, af1);
            unpack2(tf, lo, hi);
            float gf = iv.y + lo + hi;
            ull tg = add2(ag0, ag1);
            unpack2(tg, lo, hi);
            float gg = iv.z + lo + hi;
            ull to = add2(ao0, ao1);
            unpack2(to, lo, hi);
            float go = iv.w + lo + hi;

            float si = fmaf(0.5f, tanh_fast(gi), 0.5f);   // prescaled sigmoid
            float sf = fmaf(0.5f, tanh_fast(gf), 0.5f);
            float so = fmaf(0.5f, tanh_fast(go), 0.5f);
            float tgg = tanh_fast(gg);
            c = fmaf(sf, c, si * tgg);
            h = so * tanh_fast(c);

            // stage this step's output head for the next iteration
            pend = fma2(pack2(h, h), wo01, 0ull);
            int cur = (int)xb[t + half];
            cur_pend = cur;
            wmask = 1.f;

            // prefetch next step's init row (selected by this step's spin)
            iv = s_init[cur * 32 + lane];
        }
    }

    // flush the last step's pend
    logp = head_update(pend, cur_pend, bo0, bo1, wmask, logp);

    if (lane == 0) {
        out[b_glob] = 0.5f * logp;
    }
}

extern "C" void kernel_launch(void* const* d_in, const int* in_sizes, int n_in,
                              void* d_out, int out_size) {
    const int* x = (const int*)d_in[0];
    const float* Wi = (const float*)d_in[1];
    const float* Wh = (const float*)d_in[2];
    const float* bh = (const float*)d_in[3];
    const float* Wo = (const float*)d_in[4];
    const float* bo = (const float*)d_in[5];
    float* out = (float*)d_out;

    const int batch = in_sizes[0] / LL;              // 4096
    const int blocks = batch / WARPS_PER_BLOCK;      // 1024

    lstm_kernel<<<blocks, THREADS_PER_BLOCK>>>(x, Wi, Wh, bh, Wo, bo, out);
}